// round 5
// baseline (speedup 1.0000x reference)
#include <cuda_runtime.h>
#include <cuda_bf16.h>
#include <cstdint>

// SPIL layer, fused, HMMA (mma.sync bf16 hi/lo x3) theta-GEMM.
// R5 = R4 with the aggregation column-offset bug fixed (256*half -> 128*half).
// 256 threads/CTA (8 warps), 4-point tile -> 16 warps/SM at 2 CTAs/SM.
// Warp (p, half): D[32 rows of point p][32 cols of H-half]. Cross-half r_f
// reduction via smem partials; softmax redundantly in both warps of a pair.

#define BB 8
#define NN 4096
#define KK 32
#define CC 128
#define HH 64
#define PP 32
#define PTS 4
#define ROWS 128
#define THREADS 256
#define D_THR 0.04f

// ---- smem byte layout ----
#define A_STR 136
#define B_STR 72
#define SM_A_HI 0
#define SM_A_LO (SM_A_HI + ROWS * A_STR * 2)        // 34816
#define SM_B_HI (SM_A_LO + ROWS * A_STR * 2)        // 69632
#define SM_B_LO (SM_B_HI + CC * B_STR * 2)          // 88064
#define SM_FLT  (SM_B_LO + CC * B_STR * 2)          // 106496
// float offsets in scalar region
#define F_CF    0          // 512 floats (aliased with s_agg after phase 2)
#define F_FEAT  512        // 256
#define F_RFP   768        // 256 (two halves x 128 rows)
#define F_RL    1024       // 128
#define F_SW    1152       // 4
#define F_SI    1156       // 4
#define F_CX    1160       // 12
#define F_WTS   1172       // 520
#define WM1   0
#define WM1B  96
#define WM2   128
#define WM2B  224
#define WPSI  256
#define WPSIB 320
#define WPHIB 328
#define WTHB  392
#define WZB   456
#define FLT_N  1692
#define SMEM_TOTAL (SM_FLT + FLT_N * 4)             // 113264 B -> 2 CTAs/SM

__device__ __forceinline__ uint32_t smem_to_u32(const void* p) {
    uint32_t a;
    asm("{ .reg .u64 t; cvta.to.shared.u64 t, %1; cvt.u32.u64 %0, t; }" : "=r"(a) : "l"(p));
    return a;
}
__device__ __forceinline__ void ldsm_x4(uint32_t* r, uint32_t addr) {
    asm volatile("ldmatrix.sync.aligned.m8n8.x4.shared.b16 {%0,%1,%2,%3}, [%4];"
                 : "=r"(r[0]), "=r"(r[1]), "=r"(r[2]), "=r"(r[3]) : "r"(addr));
}
__device__ __forceinline__ void ldsm_x4_t(uint32_t* r, uint32_t addr) {
    asm volatile("ldmatrix.sync.aligned.m8n8.x4.trans.shared.b16 {%0,%1,%2,%3}, [%4];"
                 : "=r"(r[0]), "=r"(r[1]), "=r"(r[2]), "=r"(r[3]) : "r"(addr));
}
__device__ __forceinline__ void mma16816(float* d, const uint32_t* a, const uint32_t* b) {
    asm volatile("mma.sync.aligned.m16n8k16.row.col.f32.bf16.bf16.f32 "
                 "{%0,%1,%2,%3}, {%4,%5,%6,%7}, {%8,%9}, {%0,%1,%2,%3};"
                 : "+f"(d[0]), "+f"(d[1]), "+f"(d[2]), "+f"(d[3])
                 : "r"(a[0]), "r"(a[1]), "r"(a[2]), "r"(a[3]), "r"(b[0]), "r"(b[1]));
}

__global__ void __launch_bounds__(THREADS, 2)
spil_kernel(const float* __restrict__ center_xyz,
            const float* __restrict__ center_features,
            const float* __restrict__ neighbor_xyz,
            const float* __restrict__ neighbor_features,
            const float* __restrict__ phi_w,  const float* __restrict__ phi_b,
            const float* __restrict__ theta_w,const float* __restrict__ theta_b,
            const float* __restrict__ m1_w,   const float* __restrict__ m1_b,
            const float* __restrict__ m2_w,   const float* __restrict__ m2_b,
            const float* __restrict__ psi_w,  const float* __restrict__ psi_b,
            const float* __restrict__ z_w,    const float* __restrict__ z_b,
            float* __restrict__ out)
{
    extern __shared__ char smem[];
    const uint32_t sbase = smem_to_u32(smem);
    char* sA_hi = smem + SM_A_HI;
    char* sA_lo = smem + SM_A_LO;
    char* sB_hi = smem + SM_B_HI;
    char* sB_lo = smem + SM_B_LO;
    float* s_f    = (float*)(smem + SM_FLT);
    float* s_cf   = s_f + F_CF;
    float* s_agg  = s_f + F_CF;     // alias: cf dead after phase 2
    float* s_feat = s_f + F_FEAT;
    float* s_rfp  = s_f + F_RFP;
    float* s_rl   = s_f + F_RL;
    float* s_sW   = s_f + F_SW;
    float* s_si   = s_f + F_SI;
    float* s_cx   = s_f + F_CX;
    float* s_wts  = s_f + F_WTS;

    const int tid = threadIdx.x;
    const int wid = tid >> 5;
    const int lid = tid & 31;
    const int p_w  = wid >> 1;       // point owned by this warp (GEMM/softmax/agg)
    const int half = wid & 1;        // H-half owned by this warp
    const int bn0 = blockIdx.x * PTS;

    // ---------------- Phase 1: load + bf16 hi/lo split into smem ----------------
    {
        const float4* nfg = (const float4*)(neighbor_features + (size_t)bn0 * KK * CC);
        #pragma unroll
        for (int it = 0; it < 16; ++it) {
            int v4 = it * THREADS + tid;
            float4 v = __ldg(&nfg[v4]);
            int flat = v4 * 4;
            int row = flat >> 7, c = flat & 127;
            __nv_bfloat162 h01 = __float22bfloat162_rn(make_float2(v.x, v.y));
            __nv_bfloat162 h23 = __float22bfloat162_rn(make_float2(v.z, v.w));
            float2 f01 = __bfloat1622float2(h01);
            float2 f23 = __bfloat1622float2(h23);
            __nv_bfloat162 l01 = __float22bfloat162_rn(make_float2(v.x - f01.x, v.y - f01.y));
            __nv_bfloat162 l23 = __float22bfloat162_rn(make_float2(v.z - f23.x, v.w - f23.y));
            uint32_t o = (uint32_t)(row * A_STR + c) * 2;
            *(__nv_bfloat162*)(sA_hi + o)     = h01;
            *(__nv_bfloat162*)(sA_hi + o + 4) = h23;
            *(__nv_bfloat162*)(sA_lo + o)     = l01;
            *(__nv_bfloat162*)(sA_lo + o + 4) = l23;
        }
        // theta_w [c][h] -> B smem [c][h]
        const float4* tg = (const float4*)theta_w;
        #pragma unroll
        for (int i = tid; i < 2048; i += THREADS) {
            float4 v = __ldg(&tg[i]);
            int c = i >> 4, h = (i & 15) * 4;
            __nv_bfloat162 h01 = __float22bfloat162_rn(make_float2(v.x, v.y));
            __nv_bfloat162 h23 = __float22bfloat162_rn(make_float2(v.z, v.w));
            float2 f01 = __bfloat1622float2(h01);
            float2 f23 = __bfloat1622float2(h23);
            __nv_bfloat162 l01 = __float22bfloat162_rn(make_float2(v.x - f01.x, v.y - f01.y));
            __nv_bfloat162 l23 = __float22bfloat162_rn(make_float2(v.z - f23.x, v.w - f23.y));
            uint32_t o = (uint32_t)(c * B_STR + h) * 2;
            *(__nv_bfloat162*)(sB_hi + o)     = h01;
            *(__nv_bfloat162*)(sB_hi + o + 4) = h23;
            *(__nv_bfloat162*)(sB_lo + o)     = l01;
            *(__nv_bfloat162*)(sB_lo + o + 4) = l23;
        }
        if (tid < 128) {
            const float4* cg = (const float4*)(center_features + (size_t)bn0 * CC);
            ((float4*)s_cf)[tid] = __ldg(&cg[tid]);
        }
        if (tid < PTS * 3) s_cx[tid] = center_xyz[(size_t)bn0 * 3 + tid];
        for (int i = tid; i < 96; i += THREADS) { s_wts[WM1 + i] = m1_w[i]; s_wts[WM2 + i] = m2_w[i]; }
        if (tid < 32) { s_wts[WM1B + tid] = m1_b[tid]; s_wts[WM2B + tid] = m2_b[tid]; }
        if (tid < 64) {
            s_wts[WPSI  + tid] = psi_w[tid];
            s_wts[WPHIB + tid] = phi_b[tid];
            s_wts[WTHB  + tid] = theta_b[tid];
            s_wts[WZB   + tid] = z_b[tid];
        }
        if (tid == 0) s_wts[WPSIB] = psi_b[0];
    }
    __syncthreads();

    // ---------------- Phase 2: pos score + mask (rows: tid<128), feat_i GEMV ----
    float score_j = 0.f, kill = 0.f;
    if (tid < 128) {
        const int p_r = tid >> 5;
        const float* nx = neighbor_xyz + ((size_t)bn0 * KK + tid) * 3;
        float nx0 = nx[0], nx1 = nx[1], nx2 = nx[2];
        float cx0 = s_cx[p_r * 3], cx1 = s_cx[p_r * 3 + 1], cx2 = s_cx[p_r * 3 + 2];
        float sj = 0.f;
        #pragma unroll
        for (int d = 0; d < PP; ++d) {
            float pj = fmaf(nx0, s_wts[WM2 + d],
                       fmaf(nx1, s_wts[WM2 + 32 + d],
                       fmaf(nx2, s_wts[WM2 + 64 + d], s_wts[WM2B + d])));
            sj = fmaf(fmaxf(pj, 0.f), s_wts[WPSI + 32 + d], sj);
        }
        score_j = sj;
        float dx = cx0 - nx0, dy = cx1 - nx1, dz = cx2 - nx2;
        float dist = sqrtf(dx * dx + dy * dy + dz * dz);
        bool masked = (cx2 == nx2) && (dist > D_THR);
        kill = masked ? 0.f : 1.f;
    }
    if (tid < PTS) {
        float cx0 = s_cx[tid * 3], cx1 = s_cx[tid * 3 + 1], cx2 = s_cx[tid * 3 + 2];
        float si = 0.f;
        #pragma unroll
        for (int d = 0; d < PP; ++d) {
            float pi = fmaf(cx0, s_wts[WM1 + d],
                       fmaf(cx1, s_wts[WM1 + 32 + d],
                       fmaf(cx2, s_wts[WM1 + 64 + d], s_wts[WM1B + d])));
            si = fmaf(fmaxf(pi, 0.f), s_wts[WPSI + d], si);
        }
        s_si[tid] = si;
    }
    {
        // feat_i: thread = (pg, h), one point each
        const int h = tid & 63, pg = tid >> 6;
        float a0 = s_wts[WPHIB + h];
        const float* pw = phi_w + h;
        const float* cf = s_cf + pg * CC;
        #pragma unroll 8
        for (int c = 0; c < CC; ++c) a0 = fmaf(cf[c], __ldg(pw + c * HH), a0);
        s_feat[pg * HH + h] = fmaxf(a0, 0.f);
    }
    __syncthreads();
    if (tid < 128) s_rl[tid] = fmaxf(s_si[tid >> 5] + score_j + s_wts[WPSIB], 0.f) * kill;

    // ---------------- Phase 3: HMMA GEMM, D[32x32] per warp ---------------------
    float acc[2][4][4];
    #pragma unroll
    for (int mt = 0; mt < 2; ++mt)
        #pragma unroll
        for (int nt = 0; nt < 4; ++nt)
            #pragma unroll
            for (int e = 0; e < 4; ++e) acc[mt][nt][e] = 0.f;

    const uint32_t a_row  = (uint32_t)(p_w * 32 + (lid & 15));
    const uint32_t a_colq = (uint32_t)((lid >> 4) * 8);
    const uint32_t aoff   = (a_row * A_STR + a_colq) * 2;
    const uint32_t b_rowl = (uint32_t)(lid & 15);
    const uint32_t b_colq = (uint32_t)((lid >> 4) * 8);

    #pragma unroll
    for (int kc = 0; kc < 8; ++kc) {
        uint32_t aA = sbase + SM_A_HI + aoff + (uint32_t)(kc * 32);
        uint32_t aL = sbase + SM_A_LO + aoff + (uint32_t)(kc * 32);
        uint32_t ah[2][4], al[2][4];
        ldsm_x4(ah[0], aA);
        ldsm_x4(ah[1], aA + 16 * A_STR * 2);
        ldsm_x4(al[0], aL);
        ldsm_x4(al[1], aL + 16 * A_STR * 2);

        uint32_t brow = (uint32_t)(kc * 16) + b_rowl;
        uint32_t bh[4][2], bl[4][2];
        #pragma unroll
        for (int q = 0; q < 2; ++q) {
            uint32_t h0 = (uint32_t)(32 * half + 16 * q) + b_colq;
            uint32_t bo = (brow * B_STR + h0) * 2;
            uint32_t r[4];
            ldsm_x4_t(r, sbase + SM_B_HI + bo);
            bh[2*q][0] = r[0]; bh[2*q][1] = r[1]; bh[2*q+1][0] = r[2]; bh[2*q+1][1] = r[3];
            ldsm_x4_t(r, sbase + SM_B_LO + bo);
            bl[2*q][0] = r[0]; bl[2*q][1] = r[1]; bl[2*q+1][0] = r[2]; bl[2*q+1][1] = r[3];
        }
        #pragma unroll
        for (int mt = 0; mt < 2; ++mt)
            #pragma unroll
            for (int nt = 0; nt < 4; ++nt) {
                mma16816(acc[mt][nt], ah[mt], bh[nt]);
                mma16816(acc[mt][nt], ah[mt], bl[nt]);
                mma16816(acc[mt][nt], al[mt], bh[nt]);
            }
    }

    // ---------------- Phase 4a: r_f partial (this warp's 32 H-cols) -------------
    {
        const int g = lid >> 2, t = lid & 3;
        const float* fp = s_feat + p_w * HH;
        float r4[4];
        #pragma unroll
        for (int mt = 0; mt < 2; ++mt) {
            float rA = 0.f, rB = 0.f;
            #pragma unroll
            for (int nt = 0; nt < 4; ++nt) {
                int h0 = 32 * half + nt * 8 + t * 2, h1 = h0 + 1;
                float tb0 = s_wts[WTHB + h0], tb1 = s_wts[WTHB + h1];
                float f0 = fp[h0], f1 = fp[h1];
                rA = fmaf(fmaxf(acc[mt][nt][0] + tb0, 0.f), f0, rA);
                rA = fmaf(fmaxf(acc[mt][nt][1] + tb1, 0.f), f1, rA);
                rB = fmaf(fmaxf(acc[mt][nt][2] + tb0, 0.f), f0, rB);
                rB = fmaf(fmaxf(acc[mt][nt][3] + tb1, 0.f), f1, rB);
            }
            r4[mt * 2]     = rA;   // local row g + 16*mt
            r4[mt * 2 + 1] = rB;   // local row g + 8 + 16*mt
        }
        #pragma unroll
        for (int i = 0; i < 4; ++i) {
            r4[i] += __shfl_xor_sync(0xffffffffu, r4[i], 1);
            r4[i] += __shfl_xor_sync(0xffffffffu, r4[i], 2);
        }
        if (t == 0) {
            float* dst = s_rfp + half * 128 + p_w * 32;
            dst[g]      = r4[0];
            dst[g + 8]  = r4[1];
            dst[g + 16] = r4[2];
            dst[g + 24] = r4[3];
        }
    }
    __syncthreads();

    // ---------------- Phase 4b: softmax (redundant in warp pair) + aggregation --
    float Wk;
    {
        int row = p_w * 32 + lid;
        float rf = (s_rfp[row] + s_rfp[128 + row]) * 0.125f;   // / sqrt(64)
        float m = rf;
        #pragma unroll
        for (int ofs = 16; ofs > 0; ofs >>= 1) m = fmaxf(m, __shfl_xor_sync(0xffffffffu, m, ofs));
        float e = s_rl[row] * __expf(rf - m);
        float s = e;
        #pragma unroll
        for (int ofs = 16; ofs > 0; ofs >>= 1) s += __shfl_xor_sync(0xffffffffu, s, ofs);
        float denom = s + 1e-8f;
        Wk = e / denom;
        if (lid == 0 && half == 0) s_sW[p_w] = s / denom;
    }
    // agg: warp handles its 64-col half; lane -> c = {64*half + 2*lid, +1}
    // byte offset = c * 2 = 128*half + 4*lid   (R4 bug was 256*half here)
    {
        float2 a01 = make_float2(0.f, 0.f);
        const uint32_t co = (uint32_t)(128 * half + 4 * lid);
        #pragma unroll
        for (int k = 0; k < KK; ++k) {
            float wk = __shfl_sync(0xffffffffu, Wk, k);
            uint32_t o = (uint32_t)((p_w * KK + k) * A_STR) * 2 + co;
            float2 h0 = __bfloat1622float2(*(__nv_bfloat162*)(sA_hi + o));
            float2 l0 = __bfloat1622float2(*(__nv_bfloat162*)(sA_lo + o));
            a01.x = fmaf(wk, h0.x + l0.x, a01.x);
            a01.y = fmaf(wk, h0.y + l0.y, a01.y);
        }
        s_agg[p_w * CC + 64 * half + 2 * lid]     = a01.x;
        s_agg[p_w * CC + 64 * half + 2 * lid + 1] = a01.y;
    }
    __syncthreads();

    // ---------------- Phase 5: z GEMV on aggregated features + store ------------
    {
        const int h = tid & 63, pg = tid >> 6;
        float aA = s_sW[pg] * s_wts[WZB + h];
        const float* zw = z_w + h;
        const float* gA = s_agg + pg * CC;
        #pragma unroll 8
        for (int c = 0; c < CC; ++c) aA = fmaf(gA[c], __ldg(zw + c * HH), aA);
        out[(size_t)(bn0 + pg) * HH + h] = aA;
    }
}

extern "C" void kernel_launch(void* const* d_in, const int* in_sizes, int n_in,
                              void* d_out, int out_size)
{
    (void)in_sizes; (void)n_in; (void)out_size;
    const float* center_xyz        = (const float*)d_in[0];
    const float* center_features   = (const float*)d_in[1];
    const float* neighbor_xyz      = (const float*)d_in[2];
    const float* neighbor_features = (const float*)d_in[3];
    const float* phi_w   = (const float*)d_in[4];
    const float* phi_b   = (const float*)d_in[5];
    const float* theta_w = (const float*)d_in[6];
    const float* theta_b = (const float*)d_in[7];
    const float* m1_w    = (const float*)d_in[8];
    const float* m1_b    = (const float*)d_in[9];
    const float* m2_w    = (const float*)d_in[10];
    const float* m2_b    = (const float*)d_in[11];
    const float* psi_w   = (const float*)d_in[12];
    const float* psi_b   = (const float*)d_in[13];
    const float* z_w     = (const float*)d_in[14];
    const float* z_b     = (const float*)d_in[15];
    float* out = (float*)d_out;

    cudaFuncSetAttribute(spil_kernel, cudaFuncAttributeMaxDynamicSharedMemorySize, SMEM_TOTAL);
    dim3 grid(BB * NN / PTS);   // 8192
    dim3 block(THREADS);
    spil_kernel<<<grid, block, SMEM_TOTAL>>>(
        center_xyz, center_features, neighbor_xyz, neighbor_features,
        phi_w, phi_b, theta_w, theta_b, m1_w, m1_b, m2_w, m2_b,
        psi_w, psi_b, z_w, z_b, out);
}

// round 7
// speedup vs baseline: 1.2285x; 1.2285x over previous
#include <cuda_runtime.h>
#include <cuda_bf16.h>
#include <cstdint>

// SPIL layer, 6-kernel pipeline.
//   K0  : theta_w -> bf16 hi/lo global staging (exact smem B layout)
//   K1s : s_i (center pos score) per point
//   K1a : g_feat = relu(cf @ phi_w + b)                 (gemm_nh mode 0)
//   K1b : r_l = relu(s_i + s_j + psib) * mask per (n,k)
//   main: nf hi/lo split + HMMA theta GEMM + softmax + K-aggregation -> g_agg, g_sumw
//   K3  : out = g_agg @ z_w + g_sumw * z_b              (gemm_nh mode 1)
// R7 fix: device-global scratch pointers are resolved INSIDE device code
// (host-evaluated __device__ symbol addresses are UB; on GB300/ATS they
// silently alias host RAM instead of faulting -> R6's rel_err == 1.0).

#define BB 8
#define NN 4096
#define KK 32
#define CC 128
#define HH 64
#define PP 32
#define PTS 4
#define ROWS 128
#define D_THR 0.04f
#define NPTS (BB*NN)        // 32768

// ---- scratch (device globals: allocation-free) ----
__device__ float g_feat[NPTS * HH];      // 8 MB
__device__ float g_si[NPTS];
__device__ float g_rl[NPTS * KK];        // 4 MB
__device__ float g_agg[NPTS * CC];       // 16 MB
__device__ float g_sumw[NPTS];
#define B_STR 72
__device__ __align__(16) __nv_bfloat16 g_thB[2 * CC * B_STR];   // hi block, then lo block

// ---- main kernel smem byte layout (R3) ----
#define A_STR 136
#define SM_A_HI 0
#define SM_A_LO (SM_A_HI + ROWS * A_STR * 2)   // 34816
#define SM_B_HI (SM_A_LO + ROWS * A_STR * 2)   // 69632
#define SM_B_LO (SM_B_HI + CC * B_STR * 2)     // 88064
#define SM_FLT  (SM_B_LO + CC * B_STR * 2)     // 106496
#define F_FEAT 0      // 256 floats
#define F_RF   256    // 128
#define F_THB  384    // 64
#define SMEM_TOTAL (SM_FLT + 448 * 4)          // 108288 B -> 2 CTAs/SM

__device__ __forceinline__ uint32_t smem_to_u32(const void* p) {
    uint32_t a;
    asm("{ .reg .u64 t; cvta.to.shared.u64 t, %1; cvt.u32.u64 %0, t; }" : "=r"(a) : "l"(p));
    return a;
}
__device__ __forceinline__ void ldsm_x4(uint32_t* r, uint32_t addr) {
    asm volatile("ldmatrix.sync.aligned.m8n8.x4.shared.b16 {%0,%1,%2,%3}, [%4];"
                 : "=r"(r[0]), "=r"(r[1]), "=r"(r[2]), "=r"(r[3]) : "r"(addr));
}
__device__ __forceinline__ void ldsm_x4_t(uint32_t* r, uint32_t addr) {
    asm volatile("ldmatrix.sync.aligned.m8n8.x4.trans.shared.b16 {%0,%1,%2,%3}, [%4];"
                 : "=r"(r[0]), "=r"(r[1]), "=r"(r[2]), "=r"(r[3]) : "r"(addr));
}
__device__ __forceinline__ void mma16816(float* d, const uint32_t* a, const uint32_t* b) {
    asm volatile("mma.sync.aligned.m16n8k16.row.col.f32.bf16.bf16.f32 "
                 "{%0,%1,%2,%3}, {%4,%5,%6,%7}, {%8,%9}, {%0,%1,%2,%3};"
                 : "+f"(d[0]), "+f"(d[1]), "+f"(d[2]), "+f"(d[3])
                 : "r"(a[0]), "r"(a[1]), "r"(a[2]), "r"(a[3]), "r"(b[0]), "r"(b[1]));
}

// ================= K0: theta -> bf16 hi/lo staging =================
__global__ void k0_theta(const float* __restrict__ tw) {
    int id = blockIdx.x * 256 + threadIdx.x;
    if (id < CC * HH) {
        int c = id >> 6, h = id & 63;
        float v = tw[id];
        __nv_bfloat16 hi = __float2bfloat16_rn(v);
        __nv_bfloat16 lo = __float2bfloat16_rn(v - __bfloat162float(hi));
        g_thB[c * B_STR + h] = hi;
        g_thB[CC * B_STR + c * B_STR + h] = lo;
    }
}

// ================= K1s: center positional score s_i =================
__global__ void __launch_bounds__(256) k1_si(const float* __restrict__ cxyz,
                                             const float* __restrict__ m1w,
                                             const float* __restrict__ m1b,
                                             const float* __restrict__ psiw) {
    __shared__ float sw[96], sb[32], sp[32];
    int tid = threadIdx.x;
    if (tid < 96) sw[tid] = m1w[tid];
    if (tid < 32) { sb[tid] = m1b[tid]; sp[tid] = psiw[tid]; }
    __syncthreads();
    int id = blockIdx.x * 256 + tid;
    float x = cxyz[id * 3], y = cxyz[id * 3 + 1], z = cxyz[id * 3 + 2];
    float si = 0.f;
    #pragma unroll
    for (int d = 0; d < PP; ++d) {
        float pi = fmaf(x, sw[d], fmaf(y, sw[32 + d], fmaf(z, sw[64 + d], sb[d])));
        si = fmaf(fmaxf(pi, 0.f), sp[d], si);
    }
    g_si[id] = si;
}

// ================= K1b: r_l per (n,k), masked + relu'd =================
__global__ void __launch_bounds__(256) k1_rl(const float* __restrict__ cxyz,
                                             const float* __restrict__ nxyz,
                                             const float* __restrict__ m2w,
                                             const float* __restrict__ m2b,
                                             const float* __restrict__ psiw,
                                             const float* __restrict__ psib) {
    __shared__ float sw[96], sb[32], sp[32], spb;
    int tid = threadIdx.x;
    if (tid < 96) sw[tid] = m2w[tid];
    if (tid < 32) { sb[tid] = m2b[tid]; sp[tid] = psiw[32 + tid]; }
    if (tid == 0) spb = psib[0];
    __syncthreads();
    int g = blockIdx.x * 256 + tid;
    int nl = g >> 5;                       // point index
    float nx = nxyz[g * 3], ny = nxyz[g * 3 + 1], nz = nxyz[g * 3 + 2];
    float cx = cxyz[nl * 3], cy = cxyz[nl * 3 + 1], cz = cxyz[nl * 3 + 2];
    float sj = 0.f;
    #pragma unroll
    for (int d = 0; d < PP; ++d) {
        float pj = fmaf(nx, sw[d], fmaf(ny, sw[32 + d], fmaf(nz, sw[64 + d], sb[d])));
        sj = fmaf(fmaxf(pj, 0.f), sp[d], sj);
    }
    float dx = cx - nx, dy = cy - ny, dz = cz - nz;
    float dist = sqrtf(dx * dx + dy * dy + dz * dz);
    bool masked = (cz == nz) && (dist > D_THR);
    float kill = masked ? 0.f : 1.f;
    g_rl[g] = fmaxf(g_si[nl] + sj + spb, 0.f) * kill;
}

// ========== shared tiled GEMV kernel (device-side global resolution) ==========
// mode 0: g_feat = relu(Aparam @ W + bias)         (Aparam = center_features)
// mode 1: outparam = g_agg @ W + g_sumw[r] * bias  (outparam = d_out)
__global__ void __launch_bounds__(256) gemm_nh(const float* __restrict__ Aparam,
                                               const float* __restrict__ W,
                                               const float* __restrict__ bias,
                                               float* __restrict__ outparam, int mode) {
    __shared__ float sW[CC * 68];
    __shared__ float sA[16 * CC];
    __shared__ float sb[HH];
    __shared__ float ss[16];
    // resolve scratch pointers in DEVICE code (host-side symbol address is UB)
    const float* A = (mode == 0) ? Aparam : g_agg;
    float* outp    = (mode == 0) ? g_feat : outparam;
    int tid = threadIdx.x;
    int r0 = blockIdx.x * 16;
    for (int i = tid; i < 2048; i += 256) {
        float4 v = __ldg(&((const float4*)W)[i]);
        int c = i >> 4, h4 = (i & 15) * 4;
        *(float4*)&sW[c * 68 + h4] = v;
    }
    for (int i = tid; i < 512; i += 256) {
        float4 v = __ldg(&((const float4*)(A + (size_t)r0 * CC))[i]);
        int r = i >> 5, c4 = (i & 31) * 4;
        *(float4*)&sA[r * CC + c4] = v;
    }
    if (tid < HH) sb[tid] = bias[tid];
    if (mode == 1 && tid < 16) ss[tid] = g_sumw[r0 + tid];
    __syncthreads();
    int r = tid >> 4, hq = tid & 15, h = hq * 4;
    float4 bv = *(float4*)&sb[h];
    float a0, a1, a2, a3;
    if (mode == 1) {
        float sc = ss[r];
        a0 = sc * bv.x; a1 = sc * bv.y; a2 = sc * bv.z; a3 = sc * bv.w;
    } else {
        a0 = bv.x; a1 = bv.y; a2 = bv.z; a3 = bv.w;
    }
    const float* ar = sA + r * CC;
    #pragma unroll 8
    for (int c = 0; c < CC; ++c) {
        float av = ar[c];
        float4 w = *(float4*)&sW[c * 68 + h];
        a0 = fmaf(av, w.x, a0);
        a1 = fmaf(av, w.y, a1);
        a2 = fmaf(av, w.z, a2);
        a3 = fmaf(av, w.w, a3);
    }
    if (mode == 0) {
        a0 = fmaxf(a0, 0.f); a1 = fmaxf(a1, 0.f);
        a2 = fmaxf(a2, 0.f); a3 = fmaxf(a3, 0.f);
    }
    float4 o = make_float4(a0, a1, a2, a3);
    *(float4*)&outp[(size_t)(r0 + r) * HH + h] = o;
}

// ================= main: nf split + HMMA GEMM + softmax + aggregation =================
__global__ void __launch_bounds__(128)
spil_main(const float* __restrict__ neighbor_features,
          const float* __restrict__ theta_b)
{
    extern __shared__ char smem[];
    const uint32_t sbase = smem_to_u32(smem);
    char* sA_hi = smem + SM_A_HI;
    char* sA_lo = smem + SM_A_LO;
    float* s_f    = (float*)(smem + SM_FLT);
    float* s_feat = s_f + F_FEAT;
    float* s_rf   = s_f + F_RF;
    float* s_thb  = s_f + F_THB;

    const int tid = threadIdx.x;
    const int wid = tid >> 5;
    const int lid = tid & 31;
    const int bn0 = blockIdx.x * PTS;

    const float r_l = __ldg(&g_rl[blockIdx.x * 128 + tid]);

    // ---- Phase 1: loads ----
    {
        const float4* nfg = (const float4*)(neighbor_features + (size_t)bn0 * KK * CC);
        #pragma unroll
        for (int it = 0; it < 32; ++it) {
            int v4 = it * 128 + tid;
            float4 v = __ldg(&nfg[v4]);
            int flat = v4 * 4;
            int row = flat >> 7, c = flat & 127;
            __nv_bfloat162 h01 = __float22bfloat162_rn(make_float2(v.x, v.y));
            __nv_bfloat162 h23 = __float22bfloat162_rn(make_float2(v.z, v.w));
            float2 f01 = __bfloat1622float2(h01);
            float2 f23 = __bfloat1622float2(h23);
            __nv_bfloat162 l01 = __float22bfloat162_rn(make_float2(v.x - f01.x, v.y - f01.y));
            __nv_bfloat162 l23 = __float22bfloat162_rn(make_float2(v.z - f23.x, v.w - f23.y));
            uint32_t o = (uint32_t)(row * A_STR + c) * 2;
            *(__nv_bfloat162*)(sA_hi + o)     = h01;
            *(__nv_bfloat162*)(sA_hi + o + 4) = h23;
            *(__nv_bfloat162*)(sA_lo + o)     = l01;
            *(__nv_bfloat162*)(sA_lo + o + 4) = l23;
        }
        // theta bf16 hi/lo: raw copy of pre-staged buffer (covers B_HI then B_LO)
        const uint4* tb = (const uint4*)g_thB;
        uint4* bd = (uint4*)(smem + SM_B_HI);
        #pragma unroll
        for (int i = tid; i < 2304; i += 128) bd[i] = __ldg(&tb[i]);
        // feat rows for this CTA's 4 points
        if (tid < 64)
            ((uint4*)s_feat)[tid] = __ldg(&((const uint4*)(g_feat + (size_t)bn0 * HH))[tid]);
        if (tid < 64) s_thb[tid] = theta_b[tid];
    }
    __syncthreads();

    // ---- Phase 3: HMMA GEMM (verbatim R3): D[32x64] per warp ----
    float acc[2][8][4];
    #pragma unroll
    for (int mt = 0; mt < 2; ++mt)
        #pragma unroll
        for (int nt = 0; nt < 8; ++nt)
            #pragma unroll
            for (int e = 0; e < 4; ++e) acc[mt][nt][e] = 0.f;

    const uint32_t a_row  = (uint32_t)(wid * 32 + (lid & 15));
    const uint32_t a_colq = (uint32_t)((lid >> 4) * 8);
    const uint32_t aoff   = (a_row * A_STR + a_colq) * 2;
    const uint32_t b_rowl = (uint32_t)(lid & 15);
    const uint32_t b_colq = (uint32_t)((lid >> 4) * 8);

    #pragma unroll
    for (int kc = 0; kc < 8; ++kc) {
        uint32_t aA = sbase + SM_A_HI + aoff + (uint32_t)(kc * 32);
        uint32_t aL = sbase + SM_A_LO + aoff + (uint32_t)(kc * 32);
        uint32_t ah[2][4], al[2][4];
        ldsm_x4(ah[0], aA);
        ldsm_x4(ah[1], aA + 16 * A_STR * 2);
        ldsm_x4(al[0], aL);
        ldsm_x4(al[1], aL + 16 * A_STR * 2);

        uint32_t brow = (uint32_t)(kc * 16) + b_rowl;
        uint32_t bh[8][2], bl[8][2];
        #pragma unroll
        for (int p = 0; p < 4; ++p) {
            uint32_t bo = (brow * B_STR + 16 * p + b_colq) * 2;
            uint32_t r[4];
            ldsm_x4_t(r, sbase + SM_B_HI + bo);
            bh[2*p][0] = r[0]; bh[2*p][1] = r[1]; bh[2*p+1][0] = r[2]; bh[2*p+1][1] = r[3];
            ldsm_x4_t(r, sbase + SM_B_LO + bo);
            bl[2*p][0] = r[0]; bl[2*p][1] = r[1]; bl[2*p+1][0] = r[2]; bl[2*p+1][1] = r[3];
        }
        #pragma unroll
        for (int mt = 0; mt < 2; ++mt)
            #pragma unroll
            for (int nt = 0; nt < 8; ++nt) {
                mma16816(acc[mt][nt], ah[mt], bh[nt]);
                mma16816(acc[mt][nt], ah[mt], bl[nt]);
                mma16816(acc[mt][nt], al[mt], bh[nt]);
            }
    }

    // ---- Phase 4: r_f reduction in fragment layout (verbatim R3) ----
    {
        const int g = lid >> 2, t = lid & 3;
        const float* fp = s_feat + wid * HH;
        float r4[4];
        #pragma unroll
        for (int mt = 0; mt < 2; ++mt) {
            float rA = 0.f, rB = 0.f;
            #pragma unroll
            for (int nt = 0; nt < 8; ++nt) {
                int h0 = nt * 8 + t * 2, h1 = h0 + 1;
                float tb0 = s_thb[h0], tb1 = s_thb[h1];
                float f0 = fp[h0], f1 = fp[h1];
                rA = fmaf(fmaxf(acc[mt][nt][0] + tb0, 0.f), f0, rA);
                rA = fmaf(fmaxf(acc[mt][nt][1] + tb1, 0.f), f1, rA);
                rB = fmaf(fmaxf(acc[mt][nt][2] + tb0, 0.f), f0, rB);
                rB = fmaf(fmaxf(acc[mt][nt][3] + tb1, 0.f), f1, rB);
            }
            r4[mt * 2]     = rA;
            r4[mt * 2 + 1] = rB;
        }
        #pragma unroll
        for (int i = 0; i < 4; ++i) {
            r4[i] += __shfl_xor_sync(0xffffffffu, r4[i], 1);
            r4[i] += __shfl_xor_sync(0xffffffffu, r4[i], 2);
        }
        if (t == 0) {
            s_rf[wid * 32 + g]      = r4[0];
            s_rf[wid * 32 + g + 8]  = r4[1];
            s_rf[wid * 32 + g + 16] = r4[2];
            s_rf[wid * 32 + g + 24] = r4[3];
        }
    }
    __syncwarp();

    // ---- softmax (warp w <-> point w, lane <-> k) ----
    float Wk;
    {
        float rf = s_rf[wid * 32 + lid] * 0.125f;      // / sqrt(64)
        float m = rf;
        #pragma unroll
        for (int ofs = 16; ofs > 0; ofs >>= 1) m = fmaxf(m, __shfl_xor_sync(0xffffffffu, m, ofs));
        float e = r_l * __expf(rf - m);
        float s = e;
        #pragma unroll
        for (int ofs = 16; ofs > 0; ofs >>= 1) s += __shfl_xor_sync(0xffffffffu, s, ofs);
        float denom = s + 1e-8f;
        Wk = e / denom;
        if (lid == 0) g_sumw[bn0 + wid] = s / denom;
    }

    // ---- aggregation (verbatim R3 addressing) -> direct global store ----
    {
        float2 a01 = make_float2(0.f, 0.f), a23 = make_float2(0.f, 0.f);
        #pragma unroll
        for (int k = 0; k < KK; ++k) {
            float wk = __shfl_sync(0xffffffffu, Wk, k);
            uint32_t ro = (uint32_t)((wid * KK + k) * A_STR) * 2;
            uint32_t o0 = ro + (uint32_t)(4 * lid);
            uint32_t o1 = o0 + 128;
            float2 h0 = __bfloat1622float2(*(__nv_bfloat162*)(sA_hi + o0));
            float2 l0 = __bfloat1622float2(*(__nv_bfloat162*)(sA_lo + o0));
            float2 h1 = __bfloat1622float2(*(__nv_bfloat162*)(sA_hi + o1));
            float2 l1 = __bfloat1622float2(*(__nv_bfloat162*)(sA_lo + o1));
            a01.x = fmaf(wk, h0.x + l0.x, a01.x);
            a01.y = fmaf(wk, h0.y + l0.y, a01.y);
            a23.x = fmaf(wk, h1.x + l1.x, a23.x);
            a23.y = fmaf(wk, h1.y + l1.y, a23.y);
        }
        float* dst = g_agg + (size_t)(bn0 + wid) * CC;
        *(float2*)&dst[2 * lid]      = a01;
        *(float2*)&dst[64 + 2 * lid] = a23;
    }
}

extern "C" void kernel_launch(void* const* d_in, const int* in_sizes, int n_in,
                              void* d_out, int out_size)
{
    (void)in_sizes; (void)n_in; (void)out_size;
    const float* center_xyz        = (const float*)d_in[0];
    const float* center_features   = (const float*)d_in[1];
    const float* neighbor_xyz      = (const float*)d_in[2];
    const float* neighbor_features = (const float*)d_in[3];
    const float* phi_w   = (const float*)d_in[4];
    const float* phi_b   = (const float*)d_in[5];
    const float* theta_w = (const float*)d_in[6];
    const float* theta_b = (const float*)d_in[7];
    const float* m1_w    = (const float*)d_in[8];
    const float* m1_b    = (const float*)d_in[9];
    const float* m2_w    = (const float*)d_in[10];
    const float* m2_b    = (const float*)d_in[11];
    const float* psi_w   = (const float*)d_in[12];
    const float* psi_b   = (const float*)d_in[13];
    const float* z_w     = (const float*)d_in[14];
    const float* z_b     = (const float*)d_in[15];
    float* out = (float*)d_out;

    cudaFuncSetAttribute(spil_main, cudaFuncAttributeMaxDynamicSharedMemorySize, SMEM_TOTAL);

    k0_theta<<<32, 256>>>(theta_w);
    k1_si<<<NPTS / 256, 256>>>(center_xyz, m1_w, m1_b, psi_w);
    gemm_nh<<<NPTS / 16, 256>>>(center_features, phi_w, phi_b, out, 0);   // writes g_feat
    k1_rl<<<NPTS * KK / 256, 256>>>(center_xyz, neighbor_xyz, m2_w, m2_b, psi_w, psi_b);
    spil_main<<<NPTS / PTS, 128, SMEM_TOTAL>>>(neighbor_features, theta_b);
    gemm_nh<<<NPTS / 16, 256>>>(center_features, z_w, z_b, out, 1);       // reads g_agg/g_sumw
}

// round 8
// speedup vs baseline: 1.3349x; 1.0866x over previous
#include <cuda_runtime.h>
#include <cuda_bf16.h>
#include <cstdint>

// SPIL layer pipeline, R8:
//   k_pre : (merged) theta->bf16 staging | s_i | g_feat = relu(cf@phi)
//   k1_rl : r_l per (n,k) masked+relu'd
//   main  : 8-warp CTA, K-split HMMA theta GEMM (warps kc 0-3 / 4-7, smem-staged
//           D reduction), softmax, column-split aggregation -> g_agg, g_sumw
//   k3    : out = g_agg @ z_w + g_sumw * z_b
// Device-global scratch resolved in device code only (R6 ATS lesson).

#define BB 8
#define NN 4096
#define KK 32
#define CC 128
#define HH 64
#define PP 32
#define PTS 4
#define ROWS 128
#define D_THR 0.04f
#define NPTS (BB*NN)        // 32768

__device__ float g_feat[NPTS * HH];
__device__ float g_si[NPTS];
__device__ float g_rl[NPTS * KK];
__device__ float g_agg[NPTS * CC];
__device__ float g_sumw[NPTS];
#define B_STR 72
__device__ __align__(16) __nv_bfloat16 g_thB[2 * CC * B_STR];

#define A_STR 136
#define SM_A_HI 0
#define SM_A_LO (SM_A_HI + ROWS * A_STR * 2)   // 34816
#define SM_B_HI (SM_A_LO + ROWS * A_STR * 2)   // 69632  (GEMM B; then D-staging)
#define SM_B_LO (SM_B_HI + CC * B_STR * 2)     // 88064
#define SM_FLT  (SM_B_LO + CC * B_STR * 2)     // 106496
#define F_FEAT 0      // 256 floats
#define F_RF   256    // 128
#define F_THB  384    // 64
#define SMEM_TOTAL (SM_FLT + 448 * 4)          // 108288 B -> 2 CTAs/SM

__device__ __forceinline__ uint32_t smem_to_u32(const void* p) {
    uint32_t a;
    asm("{ .reg .u64 t; cvta.to.shared.u64 t, %1; cvt.u32.u64 %0, t; }" : "=r"(a) : "l"(p));
    return a;
}
__device__ __forceinline__ void ldsm_x4(uint32_t* r, uint32_t addr) {
    asm volatile("ldmatrix.sync.aligned.m8n8.x4.shared.b16 {%0,%1,%2,%3}, [%4];"
                 : "=r"(r[0]), "=r"(r[1]), "=r"(r[2]), "=r"(r[3]) : "r"(addr));
}
__device__ __forceinline__ void ldsm_x4_t(uint32_t* r, uint32_t addr) {
    asm volatile("ldmatrix.sync.aligned.m8n8.x4.trans.shared.b16 {%0,%1,%2,%3}, [%4];"
                 : "=r"(r[0]), "=r"(r[1]), "=r"(r[2]), "=r"(r[3]) : "r"(addr));
}
__device__ __forceinline__ void mma16816(float* d, const uint32_t* a, const uint32_t* b) {
    asm volatile("mma.sync.aligned.m16n8k16.row.col.f32.bf16.bf16.f32 "
                 "{%0,%1,%2,%3}, {%4,%5,%6,%7}, {%8,%9}, {%0,%1,%2,%3};"
                 : "+f"(d[0]), "+f"(d[1]), "+f"(d[2]), "+f"(d[3])
                 : "r"(a[0]), "r"(a[1]), "r"(a[2]), "r"(a[3]), "r"(b[0]), "r"(b[1]));
}

// ---------- shared tiled GEMV body (phi / z projections) ----------
// mode 0: g_feat = relu(A @ W + bias)      mode 1: outp = g_agg @ W + g_sumw*bias
__device__ __forceinline__ void gemm_body(const float* __restrict__ Aparam,
                                          const float* __restrict__ W,
                                          const float* __restrict__ bias,
                                          float* __restrict__ outparam,
                                          int mode, int blk) {
    __shared__ float sW[CC * 68];
    __shared__ float sA[16 * CC];
    __shared__ float sb[HH];
    __shared__ float ss[16];
    const float* A = (mode == 0) ? Aparam : g_agg;
    float* outp    = (mode == 0) ? g_feat : outparam;
    int tid = threadIdx.x;
    int r0 = blk * 16;
    for (int i = tid; i < 2048; i += 256) {
        float4 v = __ldg(&((const float4*)W)[i]);
        *(float4*)&sW[(i >> 4) * 68 + (i & 15) * 4] = v;
    }
    for (int i = tid; i < 512; i += 256) {
        float4 v = __ldg(&((const float4*)(A + (size_t)r0 * CC))[i]);
        *(float4*)&sA[(i >> 5) * CC + (i & 31) * 4] = v;
    }
    if (tid < HH) sb[tid] = bias[tid];
    if (mode == 1 && tid < 16) ss[tid] = g_sumw[r0 + tid];
    __syncthreads();
    int r = tid >> 4, h = (tid & 15) * 4;
    float4 bv = *(float4*)&sb[h];
    float a0, a1, a2, a3;
    if (mode == 1) {
        float sc = ss[r];
        a0 = sc * bv.x; a1 = sc * bv.y; a2 = sc * bv.z; a3 = sc * bv.w;
    } else {
        a0 = bv.x; a1 = bv.y; a2 = bv.z; a3 = bv.w;
    }
    const float* ar = sA + r * CC;
    #pragma unroll 8
    for (int c = 0; c < CC; ++c) {
        float av = ar[c];
        float4 w = *(float4*)&sW[c * 68 + h];
        a0 = fmaf(av, w.x, a0); a1 = fmaf(av, w.y, a1);
        a2 = fmaf(av, w.z, a2); a3 = fmaf(av, w.w, a3);
    }
    if (mode == 0) {
        a0 = fmaxf(a0, 0.f); a1 = fmaxf(a1, 0.f);
        a2 = fmaxf(a2, 0.f); a3 = fmaxf(a3, 0.f);
    }
    *(float4*)&outp[(size_t)(r0 + r) * HH + h] = make_float4(a0, a1, a2, a3);
}

// ---------- k_pre: merged theta-staging | s_i | feat GEMV ----------
#define K1A_BLKS (NPTS / 16)     // 2048
#define SI_BLKS  (NPTS / 256)    // 128
__global__ void __launch_bounds__(256) k_pre(const float* __restrict__ cf,
                                             const float* __restrict__ phiw,
                                             const float* __restrict__ phib,
                                             const float* __restrict__ cxyz,
                                             const float* __restrict__ m1w,
                                             const float* __restrict__ m1b,
                                             const float* __restrict__ psiw,
                                             const float* __restrict__ tw) {
    int blk = blockIdx.x;
    int tid = threadIdx.x;
    if (blk < K1A_BLKS) {
        gemm_body(cf, phiw, phib, (float*)0, 0, blk);
        return;
    }
    blk -= K1A_BLKS;
    if (blk < SI_BLKS) {
        __shared__ float sw[96], sb2[32], sp[32];
        if (tid < 96) sw[tid] = m1w[tid];
        if (tid < 32) { sb2[tid] = m1b[tid]; sp[tid] = psiw[tid]; }
        __syncthreads();
        int id = blk * 256 + tid;
        float x = cxyz[id * 3], y = cxyz[id * 3 + 1], z = cxyz[id * 3 + 2];
        float si = 0.f;
        #pragma unroll
        for (int d = 0; d < PP; ++d) {
            float pi = fmaf(x, sw[d], fmaf(y, sw[32 + d], fmaf(z, sw[64 + d], sb2[d])));
            si = fmaf(fmaxf(pi, 0.f), sp[d], si);
        }
        g_si[id] = si;
        return;
    }
    blk -= SI_BLKS;
    int id = blk * 256 + tid;
    if (id < CC * HH) {
        int c = id >> 6, h = id & 63;
        float v = tw[id];
        __nv_bfloat16 hi = __float2bfloat16_rn(v);
        __nv_bfloat16 lo = __float2bfloat16_rn(v - __bfloat162float(hi));
        g_thB[c * B_STR + h] = hi;
        g_thB[CC * B_STR + c * B_STR + h] = lo;
    }
}

// ---------- k1_rl ----------
__global__ void __launch_bounds__(256) k1_rl(const float* __restrict__ cxyz,
                                             const float* __restrict__ nxyz,
                                             const float* __restrict__ m2w,
                                             const float* __restrict__ m2b,
                                             const float* __restrict__ psiw,
                                             const float* __restrict__ psib) {
    __shared__ float sw[96], sb[32], sp[32], spb;
    int tid = threadIdx.x;
    if (tid < 96) sw[tid] = m2w[tid];
    if (tid < 32) { sb[tid] = m2b[tid]; sp[tid] = psiw[32 + tid]; }
    if (tid == 0) spb = psib[0];
    __syncthreads();
    int g = blockIdx.x * 256 + tid;
    int nl = g >> 5;
    float nx = nxyz[g * 3], ny = nxyz[g * 3 + 1], nz = nxyz[g * 3 + 2];
    float cx = cxyz[nl * 3], cy = cxyz[nl * 3 + 1], cz = cxyz[nl * 3 + 2];
    float sj = 0.f;
    #pragma unroll
    for (int d = 0; d < PP; ++d) {
        float pj = fmaf(nx, sw[d], fmaf(ny, sw[32 + d], fmaf(nz, sw[64 + d], sb[d])));
        sj = fmaf(fmaxf(pj, 0.f), sp[d], sj);
    }
    float dx = cx - nx, dy = cy - ny, dz = cz - nz;
    float dist = sqrtf(dx * dx + dy * dy + dz * dz);
    bool masked = (cz == nz) && (dist > D_THR);
    g_rl[g] = fmaxf(g_si[nl] + sj + spb, 0.f) * (masked ? 0.f : 1.f);
}

// ---------- k3 ----------
__global__ void __launch_bounds__(256) k3_z(const float* __restrict__ zw,
                                            const float* __restrict__ zb,
                                            float* __restrict__ outp) {
    gemm_body((const float*)0, zw, zb, outp, 1, blockIdx.x);
}

// ---------- main: 8 warps, K-split HMMA GEMM + softmax + aggregation ----------
__global__ void __launch_bounds__(256, 2)
spil_main(const float* __restrict__ neighbor_features,
          const float* __restrict__ theta_b)
{
    extern __shared__ char smem[];
    const uint32_t sbase = smem_to_u32(smem);
    char* sA_hi = smem + SM_A_HI;
    char* sA_lo = smem + SM_A_LO;
    float* s_f    = (float*)(smem + SM_FLT);
    float* s_feat = s_f + F_FEAT;
    float* s_rf   = s_f + F_RF;
    float* s_thb  = s_f + F_THB;

    const int tid = threadIdx.x;
    const int wid = tid >> 5;
    const int lid = tid & 31;
    const int p_w   = wid & 3;     // point / row-group owned by this warp
    const int khalf = wid >> 2;    // kc range half
    const int bn0 = blockIdx.x * PTS;

    // r_l for my (point, k) row — each warp redundantly covers its point's 32 rows
    const float r_l = __ldg(&g_rl[blockIdx.x * 128 + p_w * 32 + lid]);

    // ---- Phase 1: loads + bf16 hi/lo split (256 threads) ----
    {
        const float4* nfg = (const float4*)(neighbor_features + (size_t)bn0 * KK * CC);
        #pragma unroll
        for (int it = 0; it < 16; ++it) {
            int v4 = it * 256 + tid;
            float4 v = __ldg(&nfg[v4]);
            int flat = v4 * 4;
            int row = flat >> 7, c = flat & 127;
            __nv_bfloat162 h01 = __float22bfloat162_rn(make_float2(v.x, v.y));
            __nv_bfloat162 h23 = __float22bfloat162_rn(make_float2(v.z, v.w));
            float2 f01 = __bfloat1622float2(h01);
            float2 f23 = __bfloat1622float2(h23);
            __nv_bfloat162 l01 = __float22bfloat162_rn(make_float2(v.x - f01.x, v.y - f01.y));
            __nv_bfloat162 l23 = __float22bfloat162_rn(make_float2(v.z - f23.x, v.w - f23.y));
            uint32_t o = (uint32_t)(row * A_STR + c) * 2;
            *(__nv_bfloat162*)(sA_hi + o)     = h01;
            *(__nv_bfloat162*)(sA_hi + o + 4) = h23;
            *(__nv_bfloat162*)(sA_lo + o)     = l01;
            *(__nv_bfloat162*)(sA_lo + o + 4) = l23;
        }
        const uint4* tb = (const uint4*)g_thB;
        uint4* bd = (uint4*)(smem + SM_B_HI);
        #pragma unroll
        for (int i = tid; i < 2304; i += 256) bd[i] = __ldg(&tb[i]);
        if (tid < 64)
            ((uint4*)s_feat)[tid] = __ldg(&((const uint4*)(g_feat + (size_t)bn0 * HH))[tid]);
        if (tid < 64) s_thb[tid] = theta_b[tid];
    }
    __syncthreads();

    // ---- Phase 3: K-split HMMA GEMM: warp does kc = 4*khalf .. +3, all 3 passes ----
    float acc[2][8][4];
    #pragma unroll
    for (int mt = 0; mt < 2; ++mt)
        #pragma unroll
        for (int nt = 0; nt < 8; ++nt)
            #pragma unroll
            for (int e = 0; e < 4; ++e) acc[mt][nt][e] = 0.f;

    const uint32_t a_row  = (uint32_t)(p_w * 32 + (lid & 15));
    const uint32_t a_colq = (uint32_t)((lid >> 4) * 8);
    const uint32_t aoff   = (a_row * A_STR + a_colq) * 2;
    const uint32_t b_rowl = (uint32_t)(lid & 15);
    const uint32_t b_colq = (uint32_t)((lid >> 4) * 8);

    #pragma unroll
    for (int j = 0; j < 4; ++j) {
        const int kc = 4 * khalf + j;
        uint32_t aA = sbase + SM_A_HI + aoff + (uint32_t)(kc * 32);
        uint32_t aL = sbase + SM_A_LO + aoff + (uint32_t)(kc * 32);
        uint32_t ah[2][4], al[2][4];
        ldsm_x4(ah[0], aA);
        ldsm_x4(ah[1], aA + 16 * A_STR * 2);
        ldsm_x4(al[0], aL);
        ldsm_x4(al[1], aL + 16 * A_STR * 2);

        uint32_t brow = (uint32_t)(kc * 16) + b_rowl;
        uint32_t bh[8][2], bl[8][2];
        #pragma unroll
        for (int p = 0; p < 4; ++p) {
            uint32_t bo = (brow * B_STR + 16 * p + b_colq) * 2;
            uint32_t r[4];
            ldsm_x4_t(r, sbase + SM_B_HI + bo);
            bh[2*p][0] = r[0]; bh[2*p][1] = r[1]; bh[2*p+1][0] = r[2]; bh[2*p+1][1] = r[3];
            ldsm_x4_t(r, sbase + SM_B_LO + bo);
            bl[2*p][0] = r[0]; bl[2*p][1] = r[1]; bl[2*p+1][0] = r[2]; bl[2*p+1][1] = r[3];
        }
        #pragma unroll
        for (int mt = 0; mt < 2; ++mt)
            #pragma unroll
            for (int nt = 0; nt < 8; ++nt) {
                mma16816(acc[mt][nt], ah[mt], bh[nt]);
                mma16816(acc[mt][nt], ah[mt], bl[nt]);
                mma16816(acc[mt][nt], al[mt], bh[nt]);
            }
    }
    __syncthreads();   // all B ldsm done; B region becomes D staging

    // ---- D reduction: khalf=1 stages partial D into dead B region ----
    {
        uint32_t stage = sbase + SM_B_HI + (uint32_t)(p_w * 8192) + (uint32_t)(lid * 16);
        if (khalf == 1) {
            #pragma unroll
            for (int mt = 0; mt < 2; ++mt)
                #pragma unroll
                for (int nt = 0; nt < 8; ++nt) {
                    int i = mt * 8 + nt;
                    asm volatile("st.shared.v4.f32 [%0], {%1,%2,%3,%4};"
                                 :: "r"(stage + i * 512),
                                    "f"(acc[mt][nt][0]), "f"(acc[mt][nt][1]),
                                    "f"(acc[mt][nt][2]), "f"(acc[mt][nt][3]) : "memory");
                }
        }
        __syncthreads();
        if (khalf == 0) {
            #pragma unroll
            for (int mt = 0; mt < 2; ++mt)
                #pragma unroll
                for (int nt = 0; nt < 8; ++nt) {
                    int i = mt * 8 + nt;
                    float p0, p1, p2, p3;
                    asm volatile("ld.shared.v4.f32 {%0,%1,%2,%3}, [%4];"
                                 : "=f"(p0), "=f"(p1), "=f"(p2), "=f"(p3)
                                 : "r"(stage + i * 512));
                    acc[mt][nt][0] += p0; acc[mt][nt][1] += p1;
                    acc[mt][nt][2] += p2; acc[mt][nt][3] += p3;
                }
        }
    }

    // ---- r_f reduction (khalf=0 warps, R3-verbatim fragment layout) ----
    if (khalf == 0) {
        const int g = lid >> 2, t = lid & 3;
        const float* fp = s_feat + p_w * HH;
        float r4[4];
        #pragma unroll
        for (int mt = 0; mt < 2; ++mt) {
            float rA = 0.f, rB = 0.f;
            #pragma unroll
            for (int nt = 0; nt < 8; ++nt) {
                int h0 = nt * 8 + t * 2, h1 = h0 + 1;
                float tb0 = s_thb[h0], tb1 = s_thb[h1];
                float f0 = fp[h0], f1 = fp[h1];
                rA = fmaf(fmaxf(acc[mt][nt][0] + tb0, 0.f), f0, rA);
                rA = fmaf(fmaxf(acc[mt][nt][1] + tb1, 0.f), f1, rA);
                rB = fmaf(fmaxf(acc[mt][nt][2] + tb0, 0.f), f0, rB);
                rB = fmaf(fmaxf(acc[mt][nt][3] + tb1, 0.f), f1, rB);
            }
            r4[mt * 2]     = rA;
            r4[mt * 2 + 1] = rB;
        }
        #pragma unroll
        for (int i = 0; i < 4; ++i) {
            r4[i] += __shfl_xor_sync(0xffffffffu, r4[i], 1);
            r4[i] += __shfl_xor_sync(0xffffffffu, r4[i], 2);
        }
        if (t == 0) {
            s_rf[p_w * 32 + g]      = r4[0];
            s_rf[p_w * 32 + g + 8]  = r4[1];
            s_rf[p_w * 32 + g + 16] = r4[2];
            s_rf[p_w * 32 + g + 24] = r4[3];
        }
    }
    __syncthreads();

    // ---- softmax (redundant in both khalf warps of a point) ----
    float Wk;
    {
        float rf = s_rf[p_w * 32 + lid] * 0.125f;
        float m = rf;
        #pragma unroll
        for (int ofs = 16; ofs > 0; ofs >>= 1) m = fmaxf(m, __shfl_xor_sync(0xffffffffu, m, ofs));
        float e = r_l * __expf(rf - m);
        float s = e;
        #pragma unroll
        for (int ofs = 16; ofs > 0; ofs >>= 1) s += __shfl_xor_sync(0xffffffffu, s, ofs);
        float denom = s + 1e-8f;
        Wk = e / denom;
        if (khalf == 0 && lid == 0) g_sumw[bn0 + p_w] = s / denom;
    }

    // ---- aggregation: warp covers its 64-column half (c = 64*khalf + 2*lid, +1) ----
    {
        float2 a01 = make_float2(0.f, 0.f);
        const uint32_t co = (uint32_t)(128 * khalf + 4 * lid);
        #pragma unroll
        for (int k = 0; k < KK; ++k) {
            float wk = __shfl_sync(0xffffffffu, Wk, k);
            uint32_t o = (uint32_t)((p_w * KK + k) * A_STR) * 2 + co;
            float2 h0 = __bfloat1622float2(*(__nv_bfloat162*)(sA_hi + o));
            float2 l0 = __bfloat1622float2(*(__nv_bfloat162*)(sA_lo + o));
            a01.x = fmaf(wk, h0.x + l0.x, a01.x);
            a01.y = fmaf(wk, h0.y + l0.y, a01.y);
        }
        float* dst = g_agg + (size_t)(bn0 + p_w) * CC + 64 * khalf;
        *(float2*)&dst[2 * lid] = a01;
    }
}

extern "C" void kernel_launch(void* const* d_in, const int* in_sizes, int n_in,
                              void* d_out, int out_size)
{
    (void)in_sizes; (void)n_in; (void)out_size;
    const float* center_xyz        = (const float*)d_in[0];
    const float* center_features   = (const float*)d_in[1];
    const float* neighbor_xyz      = (const float*)d_in[2];
    const float* neighbor_features = (const float*)d_in[3];
    const float* phi_w   = (const float*)d_in[4];
    const float* phi_b   = (const float*)d_in[5];
    const float* theta_w = (const float*)d_in[6];
    const float* theta_b = (const float*)d_in[7];
    const float* m1_w    = (const float*)d_in[8];
    const float* m1_b    = (const float*)d_in[9];
    const float* m2_w    = (const float*)d_in[10];
    const float* m2_b    = (const float*)d_in[11];
    const float* psi_w   = (const float*)d_in[12];
    const float* psi_b   = (const float*)d_in[13];
    const float* z_w     = (const float*)d_in[14];
    const float* z_b     = (const float*)d_in[15];
    float* out = (float*)d_out;

    cudaFuncSetAttribute(spil_main, cudaFuncAttributeMaxDynamicSharedMemorySize, SMEM_TOTAL);

    k_pre<<<K1A_BLKS + SI_BLKS + 32, 256>>>(center_features, phi_w, phi_b,
                                            center_xyz, m1_w, m1_b, psi_w, theta_w);
    k1_rl<<<NPTS * KK / 256, 256>>>(center_xyz, neighbor_xyz, m2_w, m2_b, psi_w, psi_b);
    spil_main<<<NPTS / PTS, 256, SMEM_TOTAL>>>(neighbor_features, theta_b);
    k3_z<<<NPTS / 16, 256>>>(z_w, z_b, out);
}

// round 9
// speedup vs baseline: 1.6136x; 1.2088x over previous
#include <cuda_runtime.h>
#include <cuda_bf16.h>
#include <cstdint>

// SPIL layer pipeline, R9:
//   k_pre : stage theta/phi/z -> bf16 hi/lo  |  s_i per point
//   aux<0>: g_feat = relu(cf @ phi_w + b)        [HMMA, K-split 8-warp]
//   k1_rl : r_l per (n,k) masked+relu'd
//   main  : R8-verbatim K-split HMMA theta GEMM + softmax + agg -> g_agg, g_sumw
//   aux<1>: out = g_agg @ z_w + g_sumw * z_b     [HMMA]
// R8 lesson: scalar GEMV tiles are smem-crossbar bound (L1 79%, 44us) ->
// run the 32768x128x64 projections on tensor cores with the same layout code.

#define BB 8
#define NN 4096
#define KK 32
#define CC 128
#define HH 64
#define PP 32
#define PTS 4
#define ROWS 128
#define D_THR 0.04f
#define NPTS (BB*NN)        // 32768

__device__ float g_feat[NPTS * HH];
__device__ float g_si[NPTS];
__device__ float g_rl[NPTS * KK];
__device__ float g_agg[NPTS * CC];
__device__ float g_sumw[NPTS];
#define B_STR 72
__device__ __align__(16) __nv_bfloat16 g_thB[2 * CC * B_STR];
__device__ __align__(16) __nv_bfloat16 g_phB[2 * CC * B_STR];
__device__ __align__(16) __nv_bfloat16 g_zB [2 * CC * B_STR];

#define A_STR 136
#define SM_A_HI 0
#define SM_A_LO (SM_A_HI + ROWS * A_STR * 2)   // 34816
#define SM_B_HI (SM_A_LO + ROWS * A_STR * 2)   // 69632  (GEMM B; then D-staging)
#define SM_B_LO (SM_B_HI + CC * B_STR * 2)     // 88064
#define SM_FLT  (SM_B_LO + CC * B_STR * 2)     // 106496
#define F_FEAT 0      // 256 floats (main) / bias+sumw (aux)
#define F_RF   256    // 128
#define F_THB  384    // 64
#define SMEM_TOTAL (SM_FLT + 448 * 4)          // 108288 B -> 2 CTAs/SM
// aux scalar region (within F area): bias[64] at F_FEAT, sumw[128] at F_FEAT+64
#define F_BIAS 0
#define F_SUMW 64

__device__ __forceinline__ uint32_t smem_to_u32(const void* p) {
    uint32_t a;
    asm("{ .reg .u64 t; cvta.to.shared.u64 t, %1; cvt.u32.u64 %0, t; }" : "=r"(a) : "l"(p));
    return a;
}
__device__ __forceinline__ void ldsm_x4(uint32_t* r, uint32_t addr) {
    asm volatile("ldmatrix.sync.aligned.m8n8.x4.shared.b16 {%0,%1,%2,%3}, [%4];"
                 : "=r"(r[0]), "=r"(r[1]), "=r"(r[2]), "=r"(r[3]) : "r"(addr));
}
__device__ __forceinline__ void ldsm_x4_t(uint32_t* r, uint32_t addr) {
    asm volatile("ldmatrix.sync.aligned.m8n8.x4.trans.shared.b16 {%0,%1,%2,%3}, [%4];"
                 : "=r"(r[0]), "=r"(r[1]), "=r"(r[2]), "=r"(r[3]) : "r"(addr));
}
__device__ __forceinline__ void mma16816(float* d, const uint32_t* a, const uint32_t* b) {
    asm volatile("mma.sync.aligned.m16n8k16.row.col.f32.bf16.bf16.f32 "
                 "{%0,%1,%2,%3}, {%4,%5,%6,%7}, {%8,%9}, {%0,%1,%2,%3};"
                 : "+f"(d[0]), "+f"(d[1]), "+f"(d[2]), "+f"(d[3])
                 : "r"(a[0]), "r"(a[1]), "r"(a[2]), "r"(a[3]), "r"(b[0]), "r"(b[1]));
}

// ---- shared GEMM building blocks (used by main and aux) ----
// Phase-1 A split: 128 rows x 128 fp32 -> sA_hi/sA_lo (256 threads, 16 iters)
__device__ __forceinline__ void split_A(const float* __restrict__ src,
                                        char* sA_hi, char* sA_lo, int tid) {
    const float4* ag = (const float4*)src;
    #pragma unroll
    for (int it = 0; it < 16; ++it) {
        int v4 = it * 256 + tid;
        float4 v = __ldg(&ag[v4]);
        int flat = v4 * 4;
        int row = flat >> 7, c = flat & 127;
        __nv_bfloat162 h01 = __float22bfloat162_rn(make_float2(v.x, v.y));
        __nv_bfloat162 h23 = __float22bfloat162_rn(make_float2(v.z, v.w));
        float2 f01 = __bfloat1622float2(h01);
        float2 f23 = __bfloat1622float2(h23);
        __nv_bfloat162 l01 = __float22bfloat162_rn(make_float2(v.x - f01.x, v.y - f01.y));
        __nv_bfloat162 l23 = __float22bfloat162_rn(make_float2(v.z - f23.x, v.w - f23.y));
        uint32_t o = (uint32_t)(row * A_STR + c) * 2;
        *(__nv_bfloat162*)(sA_hi + o)     = h01;
        *(__nv_bfloat162*)(sA_hi + o + 4) = h23;
        *(__nv_bfloat162*)(sA_lo + o)     = l01;
        *(__nv_bfloat162*)(sA_lo + o + 4) = l23;
    }
}

// K-split GEMM core + smem D-reduction. After return, khalf=0 warps hold full D.
__device__ __forceinline__ void gemm_ksplit(uint32_t sbase, int p_w, int khalf,
                                            int lid, float acc[2][8][4]) {
    #pragma unroll
    for (int mt = 0; mt < 2; ++mt)
        #pragma unroll
        for (int nt = 0; nt < 8; ++nt)
            #pragma unroll
            for (int e = 0; e < 4; ++e) acc[mt][nt][e] = 0.f;

    const uint32_t a_row  = (uint32_t)(p_w * 32 + (lid & 15));
    const uint32_t a_colq = (uint32_t)((lid >> 4) * 8);
    const uint32_t aoff   = (a_row * A_STR + a_colq) * 2;
    const uint32_t b_rowl = (uint32_t)(lid & 15);
    const uint32_t b_colq = (uint32_t)((lid >> 4) * 8);

    #pragma unroll
    for (int j = 0; j < 4; ++j) {
        const int kc = 4 * khalf + j;
        uint32_t aA = sbase + SM_A_HI + aoff + (uint32_t)(kc * 32);
        uint32_t aL = sbase + SM_A_LO + aoff + (uint32_t)(kc * 32);
        uint32_t ah[2][4], al[2][4];
        ldsm_x4(ah[0], aA);
        ldsm_x4(ah[1], aA + 16 * A_STR * 2);
        ldsm_x4(al[0], aL);
        ldsm_x4(al[1], aL + 16 * A_STR * 2);

        uint32_t brow = (uint32_t)(kc * 16) + b_rowl;
        uint32_t bh[8][2], bl[8][2];
        #pragma unroll
        for (int p = 0; p < 4; ++p) {
            uint32_t bo = (brow * B_STR + 16 * p + b_colq) * 2;
            uint32_t r[4];
            ldsm_x4_t(r, sbase + SM_B_HI + bo);
            bh[2*p][0] = r[0]; bh[2*p][1] = r[1]; bh[2*p+1][0] = r[2]; bh[2*p+1][1] = r[3];
            ldsm_x4_t(r, sbase + SM_B_LO + bo);
            bl[2*p][0] = r[0]; bl[2*p][1] = r[1]; bl[2*p+1][0] = r[2]; bl[2*p+1][1] = r[3];
        }
        #pragma unroll
        for (int mt = 0; mt < 2; ++mt)
            #pragma unroll
            for (int nt = 0; nt < 8; ++nt) {
                mma16816(acc[mt][nt], ah[mt], bh[nt]);
                mma16816(acc[mt][nt], ah[mt], bl[nt]);
                mma16816(acc[mt][nt], al[mt], bh[nt]);
            }
    }
    __syncthreads();   // B ldsm done -> B region becomes D staging

    uint32_t stage = sbase + SM_B_HI + (uint32_t)(p_w * 8192) + (uint32_t)(lid * 16);
    if (khalf == 1) {
        #pragma unroll
        for (int mt = 0; mt < 2; ++mt)
            #pragma unroll
            for (int nt = 0; nt < 8; ++nt) {
                int i = mt * 8 + nt;
                asm volatile("st.shared.v4.f32 [%0], {%1,%2,%3,%4};"
                             :: "r"(stage + i * 512),
                                "f"(acc[mt][nt][0]), "f"(acc[mt][nt][1]),
                                "f"(acc[mt][nt][2]), "f"(acc[mt][nt][3]) : "memory");
            }
    }
    __syncthreads();
    if (khalf == 0) {
        #pragma unroll
        for (int mt = 0; mt < 2; ++mt)
            #pragma unroll
            for (int nt = 0; nt < 8; ++nt) {
                int i = mt * 8 + nt;
                float p0, p1, p2, p3;
                asm volatile("ld.shared.v4.f32 {%0,%1,%2,%3}, [%4];"
                             : "=f"(p0), "=f"(p1), "=f"(p2), "=f"(p3)
                             : "r"(stage + i * 512));
                acc[mt][nt][0] += p0; acc[mt][nt][1] += p1;
                acc[mt][nt][2] += p2; acc[mt][nt][3] += p3;
            }
    }
}

// ---------- k_pre: bf16 weight staging (theta/phi/z) + s_i ----------
#define SI_BLKS  (NPTS / 256)    // 128
__global__ void __launch_bounds__(256) k_pre(const float* __restrict__ cxyz,
                                             const float* __restrict__ m1w,
                                             const float* __restrict__ m1b,
                                             const float* __restrict__ psiw,
                                             const float* __restrict__ tw,
                                             const float* __restrict__ phiw,
                                             const float* __restrict__ zw) {
    int blk = blockIdx.x;
    int tid = threadIdx.x;
    if (blk < SI_BLKS) {
        __shared__ float sw[96], sb2[32], sp[32];
        if (tid < 96) sw[tid] = m1w[tid];
        if (tid < 32) { sb2[tid] = m1b[tid]; sp[tid] = psiw[tid]; }
        __syncthreads();
        int id = blk * 256 + tid;
        float x = cxyz[id * 3], y = cxyz[id * 3 + 1], z = cxyz[id * 3 + 2];
        float si = 0.f;
        #pragma unroll
        for (int d = 0; d < PP; ++d) {
            float pi = fmaf(x, sw[d], fmaf(y, sw[32 + d], fmaf(z, sw[64 + d], sb2[d])));
            si = fmaf(fmaxf(pi, 0.f), sp[d], si);
        }
        g_si[id] = si;
        return;
    }
    blk -= SI_BLKS;
    int m = blk >> 5;                 // 0: theta, 1: phi, 2: z
    int id = (blk & 31) * 256 + tid;
    const float* src = (m == 0) ? tw : (m == 1) ? phiw : zw;
    __nv_bfloat16* dst = (m == 0) ? g_thB : (m == 1) ? g_phB : g_zB;
    int c = id >> 6, h = id & 63;
    float v = src[id];
    __nv_bfloat16 hi = __float2bfloat16_rn(v);
    __nv_bfloat16 lo = __float2bfloat16_rn(v - __bfloat162float(hi));
    dst[c * B_STR + h] = hi;
    dst[CC * B_STR + c * B_STR + h] = lo;
}

// ---------- k1_rl ----------
__global__ void __launch_bounds__(256) k1_rl(const float* __restrict__ cxyz,
                                             const float* __restrict__ nxyz,
                                             const float* __restrict__ m2w,
                                             const float* __restrict__ m2b,
                                             const float* __restrict__ psiw,
                                             const float* __restrict__ psib) {
    __shared__ float sw[96], sb[32], sp[32], spb;
    int tid = threadIdx.x;
    if (tid < 96) sw[tid] = m2w[tid];
    if (tid < 32) { sb[tid] = m2b[tid]; sp[tid] = psiw[32 + tid]; }
    if (tid == 0) spb = psib[0];
    __syncthreads();
    int g = blockIdx.x * 256 + tid;
    int nl = g >> 5;
    float nx = nxyz[g * 3], ny = nxyz[g * 3 + 1], nz = nxyz[g * 3 + 2];
    float cx = cxyz[nl * 3], cy = cxyz[nl * 3 + 1], cz = cxyz[nl * 3 + 2];
    float sj = 0.f;
    #pragma unroll
    for (int d = 0; d < PP; ++d) {
        float pj = fmaf(nx, sw[d], fmaf(ny, sw[32 + d], fmaf(nz, sw[64 + d], sb[d])));
        sj = fmaf(fmaxf(pj, 0.f), sp[d], sj);
    }
    float dx = cx - nx, dy = cy - ny, dz = cz - nz;
    float dist = sqrtf(dx * dx + dy * dy + dz * dz);
    bool masked = (cz == nz) && (dist > D_THR);
    g_rl[g] = fmaxf(g_si[nl] + sj + spb, 0.f) * (masked ? 0.f : 1.f);
}

// ---------- aux HMMA GEMM: 128 rows/CTA, [128x128]@[128x64] ----------
// MODE 0: g_feat = relu(cf @ phi_w + bias)
// MODE 1: outp   = g_agg @ z_w + g_sumw[row] * bias
template <int MODE>
__global__ void __launch_bounds__(256, 2)
aux_gemm(const float* __restrict__ Ain, const float* __restrict__ bias,
         float* __restrict__ outparam)
{
    extern __shared__ char smem[];
    const uint32_t sbase = smem_to_u32(smem);
    char* sA_hi = smem + SM_A_HI;
    char* sA_lo = smem + SM_A_LO;
    float* s_f    = (float*)(smem + SM_FLT);
    float* s_bias = s_f + F_BIAS;
    float* s_sumw = s_f + F_SUMW;

    const int tid = threadIdx.x;
    const int wid = tid >> 5;
    const int lid = tid & 31;
    const int p_w   = wid & 3;
    const int khalf = wid >> 2;
    const int r0 = blockIdx.x * 128;

    const float* Asrc = (MODE == 0) ? Ain : g_agg;
    const __nv_bfloat16* Bsrc = (MODE == 0) ? g_phB : g_zB;
    float* outp = (MODE == 0) ? g_feat : outparam;

    split_A(Asrc + (size_t)r0 * CC, sA_hi, sA_lo, tid);
    {
        const uint4* tb = (const uint4*)Bsrc;
        uint4* bd = (uint4*)(smem + SM_B_HI);
        #pragma unroll
        for (int i = tid; i < 2304; i += 256) bd[i] = __ldg(&tb[i]);
        if (tid < 64) s_bias[tid] = bias[tid];
        if (MODE == 1 && tid < 128) s_sumw[tid] = g_sumw[r0 + tid];
    }
    __syncthreads();

    float acc[2][8][4];
    gemm_ksplit(sbase, p_w, khalf, lid, acc);

    // epilogue + store (khalf=0 warps): row = r0 + p_w*32 + g + 8*pair + 16*mt
    if (khalf == 0) {
        const int g = lid >> 2, t = lid & 3;
        #pragma unroll
        for (int mt = 0; mt < 2; ++mt) {
            #pragma unroll
            for (int nt = 0; nt < 8; ++nt) {
                int h = nt * 8 + t * 2;
                float b0 = s_bias[h], b1 = s_bias[h + 1];
                int lr0 = p_w * 32 + g + 16 * mt;
                float v00, v01, v10, v11;
                if (MODE == 0) {
                    v00 = fmaxf(acc[mt][nt][0] + b0, 0.f);
                    v01 = fmaxf(acc[mt][nt][1] + b1, 0.f);
                    v10 = fmaxf(acc[mt][nt][2] + b0, 0.f);
                    v11 = fmaxf(acc[mt][nt][3] + b1, 0.f);
                } else {
                    float s0 = s_sumw[lr0], s1 = s_sumw[lr0 + 8];
                    v00 = fmaf(s0, b0, acc[mt][nt][0]);
                    v01 = fmaf(s0, b1, acc[mt][nt][1]);
                    v10 = fmaf(s1, b0, acc[mt][nt][2]);
                    v11 = fmaf(s1, b1, acc[mt][nt][3]);
                }
                *(float2*)&outp[(size_t)(r0 + lr0) * HH + h]     = make_float2(v00, v01);
                *(float2*)&outp[(size_t)(r0 + lr0 + 8) * HH + h] = make_float2(v10, v11);
            }
        }
    }
}

// ---------- main: R8-verbatim K-split HMMA GEMM + softmax + aggregation ----------
__global__ void __launch_bounds__(256, 2)
spil_main(const float* __restrict__ neighbor_features,
          const float* __restrict__ theta_b)
{
    extern __shared__ char smem[];
    const uint32_t sbase = smem_to_u32(smem);
    char* sA_hi = smem + SM_A_HI;
    char* sA_lo = smem + SM_A_LO;
    float* s_f    = (float*)(smem + SM_FLT);
    float* s_feat = s_f + F_FEAT;
    float* s_rf   = s_f + F_RF;
    float* s_thb  = s_f + F_THB;

    const int tid = threadIdx.x;
    const int wid = tid >> 5;
    const int lid = tid & 31;
    const int p_w   = wid & 3;
    const int khalf = wid >> 2;
    const int bn0 = blockIdx.x * PTS;

    const float r_l = __ldg(&g_rl[blockIdx.x * 128 + p_w * 32 + lid]);

    split_A(neighbor_features + (size_t)bn0 * KK * CC, sA_hi, sA_lo, tid);
    {
        const uint4* tb = (const uint4*)g_thB;
        uint4* bd = (uint4*)(smem + SM_B_HI);
        #pragma unroll
        for (int i = tid; i < 2304; i += 256) bd[i] = __ldg(&tb[i]);
        if (tid < 64)
            ((uint4*)s_feat)[tid] = __ldg(&((const uint4*)(g_feat + (size_t)bn0 * HH))[tid]);
        if (tid < 64) s_thb[tid] = theta_b[tid];
    }
    __syncthreads();

    float acc[2][8][4];
    gemm_ksplit(sbase, p_w, khalf, lid, acc);

    // r_f reduction (khalf=0 warps, fragment layout)
    if (khalf == 0) {
        const int g = lid >> 2, t = lid & 3;
        const float* fp = s_feat + p_w * HH;
        float r4[4];
        #pragma unroll
        for (int mt = 0; mt < 2; ++mt) {
            float rA = 0.f, rB = 0.f;
            #pragma unroll
            for (int nt = 0; nt < 8; ++nt) {
                int h0 = nt * 8 + t * 2, h1 = h0 + 1;
                float tb0 = s_thb[h0], tb1 = s_thb[h1];
                float f0 = fp[h0], f1 = fp[h1];
                rA = fmaf(fmaxf(acc[mt][nt][0] + tb0, 0.f), f0, rA);
                rA = fmaf(fmaxf(acc[mt][nt][1] + tb1, 0.f), f1, rA);
                rB = fmaf(fmaxf(acc[mt][nt][2] + tb0, 0.f), f0, rB);
                rB = fmaf(fmaxf(acc[mt][nt][3] + tb1, 0.f), f1, rB);
            }
            r4[mt * 2]     = rA;
            r4[mt * 2 + 1] = rB;
        }
        #pragma unroll
        for (int i = 0; i < 4; ++i) {
            r4[i] += __shfl_xor_sync(0xffffffffu, r4[i], 1);
            r4[i] += __shfl_xor_sync(0xffffffffu, r4[i], 2);
        }
        if (t == 0) {
            s_rf[p_w * 32 + g]      = r4[0];
            s_rf[p_w * 32 + g + 8]  = r4[1];
            s_rf[p_w * 32 + g + 16] = r4[2];
            s_rf[p_w * 32 + g + 24] = r4[3];
        }
    }
    __syncthreads();

    // softmax (redundant in both khalf warps of a point)
    float Wk;
    {
        float rf = s_rf[p_w * 32 + lid] * 0.125f;
        float m = rf;
        #pragma unroll
        for (int ofs = 16; ofs > 0; ofs >>= 1) m = fmaxf(m, __shfl_xor_sync(0xffffffffu, m, ofs));
        float e = r_l * __expf(rf - m);
        float s = e;
        #pragma unroll
        for (int ofs = 16; ofs > 0; ofs >>= 1) s += __shfl_xor_sync(0xffffffffu, s, ofs);
        float denom = s + 1e-8f;
        Wk = e / denom;
        if (khalf == 0 && lid == 0) g_sumw[bn0 + p_w] = s / denom;
    }

    // aggregation: warp covers its 64-column half (c = 64*khalf + 2*lid, +1)
    {
        float2 a01 = make_float2(0.f, 0.f);
        const uint32_t co = (uint32_t)(128 * khalf + 4 * lid);
        #pragma unroll
        for (int k = 0; k < KK; ++k) {
            float wk = __shfl_sync(0xffffffffu, Wk, k);
            uint32_t o = (uint32_t)((p_w * KK + k) * A_STR) * 2 + co;
            float2 h0 = __bfloat1622float2(*(__nv_bfloat162*)(sA_hi + o));
            float2 l0 = __bfloat1622float2(*(__nv_bfloat162*)(sA_lo + o));
            a01.x = fmaf(wk, h0.x + l0.x, a01.x);
            a01.y = fmaf(wk, h0.y + l0.y, a01.y);
        }
        float* dst = g_agg + (size_t)(bn0 + p_w) * CC + 64 * khalf;
        *(float2*)&dst[2 * lid] = a01;
    }
}

extern "C" void kernel_launch(void* const* d_in, const int* in_sizes, int n_in,
                              void* d_out, int out_size)
{
    (void)in_sizes; (void)n_in; (void)out_size;
    const float* center_xyz        = (const float*)d_in[0];
    const float* center_features   = (const float*)d_in[1];
    const float* neighbor_xyz      = (const float*)d_in[2];
    const float* neighbor_features = (const float*)d_in[3];
    const float* phi_w   = (const float*)d_in[4];
    const float* phi_b   = (const float*)d_in[5];
    const float* theta_w = (const float*)d_in[6];
    const float* theta_b = (const float*)d_in[7];
    const float* m1_w    = (const float*)d_in[8];
    const float* m1_b    = (const float*)d_in[9];
    const float* m2_w    = (const float*)d_in[10];
    const float* m2_b    = (const float*)d_in[11];
    const float* psi_w   = (const float*)d_in[12];
    const float* psi_b   = (const float*)d_in[13];
    const float* z_w     = (const float*)d_in[14];
    const float* z_b     = (const float*)d_in[15];
    float* out = (float*)d_out;

    cudaFuncSetAttribute(spil_main, cudaFuncAttributeMaxDynamicSharedMemorySize, SMEM_TOTAL);
    cudaFuncSetAttribute(aux_gemm<0>, cudaFuncAttributeMaxDynamicSharedMemorySize, SMEM_TOTAL);
    cudaFuncSetAttribute(aux_gemm<1>, cudaFuncAttributeMaxDynamicSharedMemorySize, SMEM_TOTAL);

    k_pre<<<SI_BLKS + 96, 256>>>(center_xyz, m1_w, m1_b, psi_w, theta_w, phi_w, z_w);
    aux_gemm<0><<<NPTS / 128, 256, SMEM_TOTAL>>>(center_features, phi_b, out);
    k1_rl<<<NPTS * KK / 256, 256>>>(center_xyz, neighbor_xyz, m2_w, m2_b, psi_w, psi_b);
    spil_main<<<NPTS / PTS, 256, SMEM_TOTAL>>>(neighbor_features, theta_b);
    aux_gemm<1><<<NPTS / 128, 256, SMEM_TOTAL>>>(center_features, z_b, out);
}